// round 6
// baseline (speedup 1.0000x reference)
#include <cuda_runtime.h>

#define DEV __device__ __forceinline__
#define BIG  1.0e30f
#define SENT 2.0f          // sentinel for fma-form CAS (data is clipped to [0,1])

__constant__ float c_mean[3] = {0.485f, 0.456f, 0.406f};
__constant__ float c_std[3]  = {0.229f, 0.224f, 0.225f};

DEV void cas(float &a, float &b) { float t = fminf(a, b); b = fmaxf(a, b); a = t; }

// Arithmetic CAS on the FMA pipe: min=0.5((a+b)-|a-b|), max=0.5((a+b)+|a-b|).
// Exact to ~1ulp for nonnegative, same-magnitude-class inputs (ours: [0,1] U {2}).
DEV void cas_fma(float &a, float &b) {
    float s = a + b;
    float d = a - b;
    float h = 0.5f * s;
    float ad = fabsf(d);
    a = fmaf(ad, -0.5f, h);
    b = fmaf(ad,  0.5f, h);
}

// Batcher odd-even merge of sorted runs x[0..P-1], x[P..N-1]; valid for N <= 2P.
template<int N, int P, int K, bool FMA>
DEV void oem_pass(float* x) {
    if constexpr (K == P) {
        #pragma unroll
        for (int i = 0; i + P < N; ++i) { if (FMA) cas_fma(x[i], x[i + P]); else cas(x[i], x[i + P]); }
    } else {
        #pragma unroll
        for (int j = K; j + K < N; j += 2 * K) {
            #pragma unroll
            for (int i = 0; i < K; ++i)
                if (i + j + K < N) { if (FMA) cas_fma(x[i + j], x[i + j + K]); else cas(x[i + j], x[i + j + K]); }
        }
    }
    if constexpr (K > 1) oem_pass<N, P, K / 2, FMA>(x);
}

// 16-CAS sort of 7 (alu pipe).
DEV void sort7(float* x) {
    cas(x[0], x[1]); cas(x[2], x[3]); cas(x[0], x[2]); cas(x[1], x[3]); cas(x[1], x[2]);
    cas(x[4], x[5]); cas(x[4], x[6]); cas(x[5], x[6]);
    cas(x[0], x[4]); cas(x[1], x[5]); cas(x[2], x[6]);
    cas(x[2], x[4]); cas(x[3], x[5]);
    cas(x[1], x[2]); cas(x[3], x[4]); cas(x[5], x[6]);
}

// S[0..27] = sorted merge of two sorted 14s — runs on the FMA pipe.
DEV void build_S(const float* A, const float* B, float* S) {
    #pragma unroll
    for (int i = 0; i < 14; ++i) S[i] = A[i];
    S[14] = SENT; S[15] = SENT;
    #pragma unroll
    for (int i = 0; i < 14; ++i) S[16 + i] = B[i];
    oem_pass<30, 16, 16, true>(S);
}

// E = merge(sorted 14 C, sorted 7 g) (alu pipe); rank-25 of S(28) U E(21):
// med = min_{i=4..25} max(S[i-1], E[24-i]); i=25 term is S[24]. Tree-reduced min.
DEV float final_select(const float* S, const float* C, const float* g) {
    float x[23];
    #pragma unroll
    for (int i = 0; i < 14; ++i) x[i] = C[i];
    x[14] = BIG; x[15] = BIG;
    #pragma unroll
    for (int i = 0; i < 7; ++i) x[16 + i] = g[i];
    oem_pass<23, 16, 16, false>(x);      // E = x[0..20]
    float t[22];
    t[0] = S[24];
    #pragma unroll
    for (int i = 4; i <= 24; ++i) t[i - 3] = fmaxf(S[i - 1], x[24 - i]);
    #pragma unroll
    for (int st = 1; st < 22; st *= 2) {
        #pragma unroll
        for (int i = 0; i + st < 22; i += 2 * st) t[i] = fminf(t[i], t[i + st]);
    }
    return t[0];
}

DEV void load_pair(const float4 (*pb)[5], int m, float* P) {
    float4 v0 = pb[m][0], v1 = pb[m][1], v2 = pb[m][2], v3 = pb[m][3];
    P[0] = v0.x;  P[1] = v0.y;  P[2]  = v0.z;  P[3]  = v0.w;
    P[4] = v1.x;  P[5] = v1.y;  P[6]  = v1.z;  P[7]  = v1.w;
    P[8] = v2.x;  P[9] = v2.y;  P[10] = v2.z;  P[11] = v2.w;
    P[12] = v3.x; P[13] = v3.y;
}

// One CTA = one output row of one (b,c) plane; 256 threads x 2 px.
__global__ __launch_bounds__(256, 4) void median7_kernel(const float* __restrict__ img,
                                                         float* __restrict__ out) {
    const int y     = blockIdx.x;        // 0..511
    const int plane = blockIdx.y;        // 0..23
    const int ch    = plane % 3;
    const float mean = c_mean[ch];
    const float sd   = c_std[ch];

    __shared__ float  srow[7][518];      // rows -> sorted columns (in place)
    __shared__ float4 pairbuf[260][5];   // pair m: 14 sorted + 2 pad in [m][0..3]; 80B row (bank-cycling)

    const float* src = img + (size_t)plane * 262144;

    #pragma unroll
    for (int r = 0; r < 7; ++r) {
        int gy = y + r - 3;
        gy = (gy < 0) ? -gy : ((gy > 511) ? 1022 - gy : gy);
        const float* rp = src + gy * 512;
        for (int c = threadIdx.x; c < 518; c += 256) {
            int gx = c - 3;
            gx = (gx < 0) ? -gx : ((gx > 511) ? 1022 - gx : gx);
            float v = fmaf(rp[gx], sd, mean);
            srow[r][c] = fminf(fmaxf(v, 0.0f), 1.0f);
        }
    }
    __syncthreads();

    // Phase 1: task m owns smem columns 2m, 2m+1 exclusively (m < 259).
    for (int m = threadIdx.x; m < 259; m += 256) {
        float x[16];
        float cb[7];
        #pragma unroll
        for (int d = 0; d < 7; ++d) { x[d] = srow[d][2 * m]; cb[d] = srow[d][2 * m + 1]; }
        sort7(x); sort7(cb);
        #pragma unroll
        for (int d = 0; d < 7; ++d) { srow[d][2 * m] = x[d]; srow[d][2 * m + 1] = cb[d]; }
        x[7] = BIG;
        #pragma unroll
        for (int d = 0; d < 7; ++d) x[8 + d] = cb[d];
        oem_pass<15, 8, 8, false>(x);    // x[0..13] sorted
        x[14] = SENT; x[15] = SENT;
        pairbuf[m][0] = make_float4(x[0],  x[1],  x[2],  x[3]);
        pairbuf[m][1] = make_float4(x[4],  x[5],  x[6],  x[7]);
        pairbuf[m][2] = make_float4(x[8],  x[9],  x[10], x[11]);
        pairbuf[m][3] = make_float4(x[12], x[13], x[14], x[15]);
    }
    __syncthreads();

    const int t = threadIdx.x;           // px0 global col = 2t

    // S = merge(pair t+1, pair t+2): shared by px0 (smem cols 2t..2t+6)
    // and px1 (smem cols 2t+1..2t+7).
    float S[30];
    {
        float P1[14], P2[14];
        load_pair(pairbuf, t + 1, P1);
        load_pair(pairbuf, t + 2, P2);
        build_S(P1, P2, S);
    }

    float m0, m1;
    {   // px0: E(pair t, lone smem col 2t+6)
        float C[14], g[7];
        load_pair(pairbuf, t, C);
        #pragma unroll
        for (int d = 0; d < 7; ++d) g[d] = srow[d][2 * t + 6];
        m0 = final_select(S, C, g);
    }
    {   // px1: E(pair t+3, lone smem col 2t+1)
        float C[14], g[7];
        load_pair(pairbuf, t + 3, C);
        #pragma unroll
        for (int d = 0; d < 7; ++d) g[d] = srow[d][2 * t + 1];
        m1 = final_select(S, C, g);
    }

    const float inv = 1.0f / sd;
    float2 o;
    o.x = (m0 - mean) * inv;
    o.y = (m1 - mean) * inv;
    *reinterpret_cast<float2*>(out + (size_t)plane * 262144 + y * 512 + 2 * t) = o;
}

extern "C" void kernel_launch(void* const* d_in, const int* in_sizes, int n_in,
                              void* d_out, int out_size) {
    const float* img  = (const float*)d_in[0];
    const float* mask = (const float*)d_in[1];
    float* out = (float*)d_out;
    const int img_elems  = in_sizes[0];
    const int mask_elems = in_sizes[1];

    dim3 grid(512, 24);
    median7_kernel<<<grid, 256>>>(img, out);
    cudaMemcpyAsync(out + img_elems, mask, (size_t)mask_elems * sizeof(float),
                    cudaMemcpyDeviceToDevice);
}

// round 7
// speedup vs baseline: 1.0441x; 1.0441x over previous
#include <cuda_runtime.h>

#define DEV __device__ __forceinline__

__constant__ float c_mean[3] = {0.485f, 0.456f, 0.406f};
__constant__ float c_std[3]  = {0.229f, 0.224f, 0.225f};

DEV void cas(float &a, float &b) { float t = fminf(a, b); b = fmaxf(a, b); a = t; }

// 16-CAS sort of 7.
DEV void sort7(float* x) {
    cas(x[0], x[1]); cas(x[2], x[3]); cas(x[0], x[2]); cas(x[1], x[3]); cas(x[1], x[2]);
    cas(x[4], x[5]); cas(x[4], x[6]); cas(x[5], x[6]);
    cas(x[0], x[4]); cas(x[1], x[5]); cas(x[2], x[6]);
    cas(x[2], x[4]); cas(x[3], x[5]);
    cas(x[1], x[2]); cas(x[3], x[4]); cas(x[5], x[6]);
}

// Pruned Batcher merge of sorted a[7], b[7] -> sorted out x[0..13].
// Derived from oem(15,8) with x[7]=+inf: sentinel CAS become renames. 21 CAS.
DEV void merge77(const float* a, const float* b, float* x /*>=15*/) {
    #pragma unroll
    for (int i = 0; i < 7; ++i) x[i] = a[i];
    #pragma unroll
    for (int i = 0; i < 7; ++i) x[8 + i] = b[i];
    // K=8
    cas(x[0], x[8]); cas(x[1], x[9]); cas(x[2], x[10]); cas(x[3], x[11]);
    cas(x[4], x[12]); cas(x[5], x[13]); cas(x[6], x[14]);
    // K=4  (sentinel at 7: rename x7 = x11)
    x[7] = x[11];
    cas(x[4], x[8]); cas(x[5], x[9]); cas(x[6], x[10]);
    // K=2  (sentinel at 11: rename x11 = x13)
    cas(x[2], x[4]); cas(x[3], x[5]); cas(x[6], x[8]); cas(x[7], x[9]);
    cas(x[10], x[12]); x[11] = x[13];
    // K=1  (sentinel at 13: rename x13 = x14)
    cas(x[1], x[2]); cas(x[3], x[4]); cas(x[5], x[6]); cas(x[7], x[8]);
    cas(x[9], x[10]); cas(x[11], x[12]); x[13] = x[14];
}

// Pruned merge of sorted A[14], B[14] -> S with ranks 3..24 valid (all we use).
// oem(30,16) with sentinels at 14,15 -> renames; final pass drops (1,2),(25,26),(27,28). 53 CAS.
DEV void build_S(const float* A, const float* B, float* x /*>=30*/) {
    #pragma unroll
    for (int i = 0; i < 14; ++i) x[i] = A[i];
    #pragma unroll
    for (int i = 0; i < 14; ++i) x[16 + i] = B[i];
    // K=16
    #pragma unroll
    for (int i = 0; i < 14; ++i) cas(x[i], x[i + 16]);
    // K=8: real (8..13)x(16..21); renames x14=x22, x15=x23
    cas(x[8], x[16]); cas(x[9], x[17]); cas(x[10], x[18]);
    cas(x[11], x[19]); cas(x[12], x[20]); cas(x[13], x[21]);
    x[14] = x[22]; x[15] = x[23];
    // K=4: j=4, j=12 real; j=20: (20,24),(21,25) real, renames x22=x26, x23=x27
    cas(x[4], x[8]); cas(x[5], x[9]); cas(x[6], x[10]); cas(x[7], x[11]);
    cas(x[12], x[16]); cas(x[13], x[17]); cas(x[14], x[18]); cas(x[15], x[19]);
    cas(x[20], x[24]); cas(x[21], x[25]);
    x[22] = x[26]; x[23] = x[27];
    // K=2: j=2..22 real; j=26 renames x26=x28, x27=x29 (x26,x27 unused after -> skip)
    cas(x[2], x[4]);  cas(x[3], x[5]);  cas(x[6], x[8]);  cas(x[7], x[9]);
    cas(x[10], x[12]); cas(x[11], x[13]); cas(x[14], x[16]); cas(x[15], x[17]);
    cas(x[18], x[20]); cas(x[19], x[21]); cas(x[22], x[24]); cas(x[23], x[25]);
    // K=1: keep (3,4)...(23,24); drop (1,2),(25,26),(27,28)
    cas(x[3], x[4]);  cas(x[5], x[6]);  cas(x[7], x[8]);  cas(x[9], x[10]);
    cas(x[11], x[12]); cas(x[13], x[14]); cas(x[15], x[16]); cas(x[17], x[18]);
    cas(x[19], x[20]); cas(x[21], x[22]); cas(x[23], x[24]);
}

// E = pruned merge of sorted C[14], sorted g[7] (oem(23,16), sentinels 14,15 -> renames,
// drop final (21,22)); ranks E[0..20] valid. 39 CAS. Then rank-25 of S(28) U E(21):
// med = min_{i=4..25} max(S[i-1], E[24-i]); i=25 term is S[24]. Tree-reduced min.
DEV float final_select(const float* S, const float* C, const float* g) {
    float x[23];
    #pragma unroll
    for (int i = 0; i < 14; ++i) x[i] = C[i];
    #pragma unroll
    for (int i = 0; i < 7; ++i) x[16 + i] = g[i];
    // K=16
    cas(x[0], x[16]); cas(x[1], x[17]); cas(x[2], x[18]); cas(x[3], x[19]);
    cas(x[4], x[20]); cas(x[5], x[21]); cas(x[6], x[22]);
    // K=8: real (8..13)x(16..21); rename x14 = x22
    cas(x[8], x[16]); cas(x[9], x[17]); cas(x[10], x[18]);
    cas(x[11], x[19]); cas(x[12], x[20]); cas(x[13], x[21]);
    x[14] = x[22];
    // K=4: j=4 real; j=12: (12,16),(13,17),(14,18) real, rename x15 = x19
    cas(x[4], x[8]); cas(x[5], x[9]); cas(x[6], x[10]); cas(x[7], x[11]);
    cas(x[12], x[16]); cas(x[13], x[17]); cas(x[14], x[18]);
    x[15] = x[19];
    // K=2: j=2,6,10,14 real; j=18: (18,20) real, rename x19 = x21
    cas(x[2], x[4]);  cas(x[3], x[5]);  cas(x[6], x[8]);  cas(x[7], x[9]);
    cas(x[10], x[12]); cas(x[11], x[13]); cas(x[14], x[16]); cas(x[15], x[17]);
    cas(x[18], x[20]);
    x[19] = x[21];
    // K=1: (1,2)...(19,20); drop (21,22)
    cas(x[1], x[2]);  cas(x[3], x[4]);  cas(x[5], x[6]);  cas(x[7], x[8]);
    cas(x[9], x[10]); cas(x[11], x[12]); cas(x[13], x[14]); cas(x[15], x[16]);
    cas(x[17], x[18]); cas(x[19], x[20]);
    // selection
    float t[22];
    t[0] = S[24];
    #pragma unroll
    for (int i = 4; i <= 24; ++i) t[i - 3] = fmaxf(S[i - 1], x[24 - i]);
    #pragma unroll
    for (int st = 1; st < 22; st *= 2) {
        #pragma unroll
        for (int i = 0; i + st < 22; i += 2 * st) t[i] = fminf(t[i], t[i + st]);
    }
    return t[0];
}

DEV void load_pair(const float4 (*pb)[5], int m, float* P) {
    float4 v0 = pb[m][0], v1 = pb[m][1], v2 = pb[m][2], v3 = pb[m][3];
    P[0] = v0.x;  P[1] = v0.y;  P[2]  = v0.z;  P[3]  = v0.w;
    P[4] = v1.x;  P[5] = v1.y;  P[6]  = v1.z;  P[7]  = v1.w;
    P[8] = v2.x;  P[9] = v2.y;  P[10] = v2.z;  P[11] = v2.w;
    P[12] = v3.x; P[13] = v3.y;
}

// One CTA = one output row of one (b,c) plane; 256 threads x 2 px.
__global__ __launch_bounds__(256, 4) void median7_kernel(const float* __restrict__ img,
                                                         float* __restrict__ out) {
    const int y     = blockIdx.x;        // 0..511
    const int plane = blockIdx.y;        // 0..23
    const int ch    = plane % 3;
    const float mean = c_mean[ch];
    const float sd   = c_std[ch];

    __shared__ float  srow[7][518];      // rows -> sorted columns (in place)
    __shared__ float4 pairbuf[260][5];   // pair m: sorted 14 in [m][0..3] (last 2 lanes pad)

    const float* src = img + (size_t)plane * 262144;

    #pragma unroll
    for (int r = 0; r < 7; ++r) {
        int gy = y + r - 3;
        gy = (gy < 0) ? -gy : ((gy > 511) ? 1022 - gy : gy);
        const float* rp = src + gy * 512;
        for (int c = threadIdx.x; c < 518; c += 256) {
            int gx = c - 3;
            gx = (gx < 0) ? -gx : ((gx > 511) ? 1022 - gx : gx);
            float v = fmaf(rp[gx], sd, mean);
            srow[r][c] = fminf(fmaxf(v, 0.0f), 1.0f);
        }
    }
    __syncthreads();

    // Phase 1: task m owns smem columns 2m, 2m+1 exclusively (m < 259).
    for (int m = threadIdx.x; m < 259; m += 256) {
        float ca[7], cb[7], x[15];
        #pragma unroll
        for (int d = 0; d < 7; ++d) { ca[d] = srow[d][2 * m]; cb[d] = srow[d][2 * m + 1]; }
        sort7(ca); sort7(cb);
        #pragma unroll
        for (int d = 0; d < 7; ++d) { srow[d][2 * m] = ca[d]; srow[d][2 * m + 1] = cb[d]; }
        merge77(ca, cb, x);              // x[0..13] sorted
        pairbuf[m][0] = make_float4(x[0],  x[1],  x[2],  x[3]);
        pairbuf[m][1] = make_float4(x[4],  x[5],  x[6],  x[7]);
        pairbuf[m][2] = make_float4(x[8],  x[9],  x[10], x[11]);
        pairbuf[m][3] = make_float4(x[12], x[13], 0.0f,  0.0f);
    }
    __syncthreads();

    const int t = threadIdx.x;           // px0 global col = 2t

    // S = merge(pair t+1, pair t+2): shared by px0 (smem cols 2t..2t+6)
    // and px1 (smem cols 2t+1..2t+7).
    float S[30];
    {
        float P1[14], P2[14];
        load_pair(pairbuf, t + 1, P1);
        load_pair(pairbuf, t + 2, P2);
        build_S(P1, P2, S);
    }

    float m0, m1;
    {   // px0: E(pair t, lone smem col 2t+6)
        float C[14], g[7];
        load_pair(pairbuf, t, C);
        #pragma unroll
        for (int d = 0; d < 7; ++d) g[d] = srow[d][2 * t + 6];
        m0 = final_select(S, C, g);
    }
    {   // px1: E(pair t+3, lone smem col 2t+1)
        float C[14], g[7];
        load_pair(pairbuf, t + 3, C);
        #pragma unroll
        for (int d = 0; d < 7; ++d) g[d] = srow[d][2 * t + 1];
        m1 = final_select(S, C, g);
    }

    const float inv = 1.0f / sd;
    float2 o;
    o.x = (m0 - mean) * inv;
    o.y = (m1 - mean) * inv;
    *reinterpret_cast<float2*>(out + (size_t)plane * 262144 + y * 512 + 2 * t) = o;
}

extern "C" void kernel_launch(void* const* d_in, const int* in_sizes, int n_in,
                              void* d_out, int out_size) {
    const float* img  = (const float*)d_in[0];
    const float* mask = (const float*)d_in[1];
    float* out = (float*)d_out;
    const int img_elems  = in_sizes[0];
    const int mask_elems = in_sizes[1];

    dim3 grid(512, 24);
    median7_kernel<<<grid, 256>>>(img, out);
    cudaMemcpyAsync(out + img_elems, mask, (size_t)mask_elems * sizeof(float),
                    cudaMemcpyDeviceToDevice);
}